// round 1
// baseline (speedup 1.0000x reference)
#include <cuda_runtime.h>

#define DIM 256
#define RPB 16          // rows (batch elements) per CTA
#define NTHREADS 256
#define KMAX 64

__global__ __launch_bounds__(NTHREADS)
void easyrec_fused(const int* __restrict__ nodes_u,
                   const int* __restrict__ nodes_v,
                   const int* __restrict__ neighbors,
                   const int* __restrict__ neighbor_counts,
                   const float* __restrict__ u2e,
                   const float* __restrict__ v2e,
                   const float* __restrict__ W,     // [D, 2D] row-major
                   const float* __restrict__ bvec,  // [D]
                   float* __restrict__ out,
                   int B)
{
    __shared__ float sv[RPB][DIM];      // gathered v2e rows      16 KB
    __shared__ int   snb[RPB][KMAX];    // neighbor indices        4 KB
    __shared__ int   scnt[RPB];
    __shared__ int   su[RPB];
    __shared__ float sred[RPB][8];      // warp partials

    const int t    = threadIdx.x;
    const int row0 = blockIdx.x * RPB;

    // ---- Phase A: load v tile + metadata (clamped for tail safety) ----
    #pragma unroll
    for (int r = 0; r < RPB; r++) {
        int b  = row0 + r; if (b >= B) b = B - 1;
        int vi = nodes_v[b];
        sv[r][t] = v2e[(size_t)vi * DIM + t];
    }
    for (int i = t; i < RPB * KMAX; i += NTHREADS) {
        int r = i >> 6, k = i & 63;
        int b = row0 + r; if (b >= B) b = B - 1;
        snb[r][k] = neighbors[(size_t)b * KMAX + k];
    }
    if (t < RPB) {
        int b = row0 + t; if (b >= B) b = B - 1;
        scnt[t] = neighbor_counts[b];
        su[t]   = nodes_u[b];
    }
    __syncthreads();

    // ---- Phase B: g[r] = v[r] @ W. Thread t owns columns t and t+256 of all rows.
    float acc1[RPB], acc2[RPB];
    #pragma unroll
    for (int r = 0; r < RPB; r++) { acc1[r] = 0.f; acc2[r] = 0.f; }

    #pragma unroll 1
    for (int j = 0; j < DIM; j += 4) {
        // 8 coalesced W loads per 4-j chunk
        float w1a = W[(size_t)(j + 0) * (2 * DIM) + t];
        float w1b = W[(size_t)(j + 1) * (2 * DIM) + t];
        float w1c = W[(size_t)(j + 2) * (2 * DIM) + t];
        float w1d = W[(size_t)(j + 3) * (2 * DIM) + t];
        float w2a = W[(size_t)(j + 0) * (2 * DIM) + DIM + t];
        float w2b = W[(size_t)(j + 1) * (2 * DIM) + DIM + t];
        float w2c = W[(size_t)(j + 2) * (2 * DIM) + DIM + t];
        float w2d = W[(size_t)(j + 3) * (2 * DIM) + DIM + t];
        #pragma unroll
        for (int r = 0; r < RPB; r++) {
            float4 v4 = *reinterpret_cast<const float4*>(&sv[r][j]);   // broadcast LDS.128
            acc1[r] = fmaf(v4.x, w1a, acc1[r]);
            acc1[r] = fmaf(v4.y, w1b, acc1[r]);
            acc1[r] = fmaf(v4.z, w1c, acc1[r]);
            acc1[r] = fmaf(v4.w, w1d, acc1[r]);
            acc2[r] = fmaf(v4.x, w2a, acc2[r]);
            acc2[r] = fmaf(v4.y, w2b, acc2[r]);
            acc2[r] = fmaf(v4.z, w2c, acc2[r]);
            acc2[r] = fmaf(v4.w, w2d, acc2[r]);
        }
    }

    const float bt = bvec[t];

    // ---- Phase C: per-row neighbor gather + score reduction ----
    #pragma unroll 1
    for (int r = 0; r < RPB; r++) {
        const int cnt = scnt[r];
        const float selfv = u2e[(size_t)su[r] * DIM + t];   // coalesced
        float partial;
        if (cnt > 0) {
            float n0 = 0.f, n1 = 0.f, n2 = 0.f, n3 = 0.f;
            int k = 0;
            for (; k + 4 <= cnt; k += 4) {
                n0 += u2e[(size_t)snb[r][k + 0] * DIM + t];
                n1 += u2e[(size_t)snb[r][k + 1] * DIM + t];
                n2 += u2e[(size_t)snb[r][k + 2] * DIM + t];
                n3 += u2e[(size_t)snb[r][k + 3] * DIM + t];
            }
            for (; k < cnt; k++) n0 += u2e[(size_t)snb[r][k] * DIM + t];
            const float nsum = (n0 + n1) + (n2 + n3);
            const float inv  = 1.f / (float)cnt;
            partial = selfv * acc1[r] + (nsum * inv) * acc2[r] + bt * sv[r][t];
        } else {
            partial = selfv * sv[r][t];   // no-neighbor fallback: self . v
        }
        // warp reduce 32 -> 1
        #pragma unroll
        for (int o = 16; o; o >>= 1)
            partial += __shfl_down_sync(0xffffffffu, partial, o);
        if ((t & 31) == 0) sred[r][t >> 5] = partial;
    }
    __syncthreads();

    if (t < RPB) {
        float s = 0.f;
        #pragma unroll
        for (int w = 0; w < 8; w++) s += sred[t][w];
        if (row0 + t < B) out[row0 + t] = s;
    }
}

extern "C" void kernel_launch(void* const* d_in, const int* in_sizes, int n_in,
                              void* d_out, int out_size)
{
    const int*   nodes_u         = (const int*)  d_in[0];
    const int*   nodes_v         = (const int*)  d_in[1];
    const int*   neighbors       = (const int*)  d_in[2];
    const int*   neighbor_counts = (const int*)  d_in[3];
    const float* u2e             = (const float*)d_in[4];
    const float* v2e             = (const float*)d_in[5];
    const float* W               = (const float*)d_in[6];
    const float* bvec            = (const float*)d_in[7];
    float*       out             = (float*)d_out;

    const int B = in_sizes[0];
    const int grid = (B + RPB - 1) / RPB;
    easyrec_fused<<<grid, NTHREADS>>>(nodes_u, nodes_v, neighbors, neighbor_counts,
                                      u2e, v2e, W, bvec, out, B);
}